// round 9
// baseline (speedup 1.0000x reference)
#include <cuda_runtime.h>

#define BATCH 4096
#define SEQT  256
#define DIN   32
#define HID   64
#define GATES 256
#define BT    32
#define NTHR  512
#define NCTA  128
#define ST    36    // padded row stride (floats) for transposed activation buffers

typedef unsigned long long u64;

// ---- global scratch: gate-quad weight layout W[k][u2][g][upar], fused biases ----
// row r in [0,256): u2 = r>>3, g = (r>>1)&3, up = r&1  ->  n = g*64 + u2*2 + up
__device__ __align__(16) float g_W0q[HID * GATES];     // Whh0 quad [64][256]
__device__ __align__(16) float g_Wx0q[DIN * GATES];    // Wih0 quad [32][256] (per-step LDG)
__device__ __align__(16) float g_W1q[2 * HID * GATES]; // [Wih1; Whh1] quad [128][256]
__device__ __align__(16) float g_b0q[GATES];           // biases in quad order
__device__ __align__(16) float g_b1q[GATES];

__global__ void prep_kernel(const float* __restrict__ Wih0, const float* __restrict__ Whh0,
                            const float* __restrict__ bih0, const float* __restrict__ bhh0,
                            const float* __restrict__ Wih1, const float* __restrict__ Whh1,
                            const float* __restrict__ bih1, const float* __restrict__ bhh1)
{
    int idx = blockIdx.x * blockDim.x + threadIdx.x;
    int stride = gridDim.x * blockDim.x;
    for (int j = idx; j < HID * GATES; j += stride) {
        int k = j / GATES, r = j % GATES;
        int n = ((r >> 1) & 3) * HID + (r >> 3) * 2 + (r & 1);
        g_W0q[j] = Whh0[n * HID + k];
    }
    for (int j = idx; j < DIN * GATES; j += stride) {
        int k = j / GATES, r = j % GATES;
        int n = ((r >> 1) & 3) * HID + (r >> 3) * 2 + (r & 1);
        g_Wx0q[j] = Wih0[n * DIN + k];
    }
    for (int j = idx; j < 2 * HID * GATES; j += stride) {
        int k = j / GATES, r = j % GATES;
        int n = ((r >> 1) & 3) * HID + (r >> 3) * 2 + (r & 1);
        g_W1q[j] = (k < HID) ? Wih1[n * HID + k] : Whh1[n * HID + (k - HID)];
    }
    for (int r = idx; r < GATES; r += stride) {
        int n = ((r >> 1) & 3) * HID + (r >> 3) * 2 + (r & 1);
        g_b0q[r] = bih0[n] + bhh0[n];
        g_b1q[r] = bih1[n] + bhh1[n];
    }
}

// ---- packed f32x2 helpers ----
__device__ __forceinline__ u64 fma2(u64 a, u64 b, u64 c) {
    u64 d;
    asm("fma.rn.f32x2 %0, %1, %2, %3;" : "=l"(d) : "l"(a), "l"(b), "l"(c));
    return d;
}
__device__ __forceinline__ u64 dup2(float x) {
    u64 d;
    asm("mov.b64 %0, {%1, %1};" : "=l"(d) : "f"(x));
    return d;
}
__device__ __forceinline__ float2 unpack2(u64 v) {
    float2 f;
    asm("mov.b64 {%0, %1}, %2;" : "=f"(f.x), "=f"(f.y) : "l"(v));
    return f;
}

// ---- fast activations (MUFU EX2/RCP, proven ~2.5e-7 end-to-end) ----
__device__ __forceinline__ float fast_ex2(float x) {
    float y; asm("ex2.approx.f32 %0, %1;" : "=f"(y) : "f"(x)); return y;
}
__device__ __forceinline__ float fast_rcp(float x) {
    float y; asm("rcp.approx.f32 %0, %1;" : "=f"(y) : "f"(x)); return y;
}
__device__ __forceinline__ float sigf(float x) {
    return fast_rcp(1.0f + fast_ex2(-1.4426950408889634f * x));
}
__device__ __forceinline__ float tanhf_fast(float x) {
    x = fminf(fmaxf(x, -15.0f), 15.0f);
    float e = fast_ex2(-2.8853900817779268f * x);  // exp(-2x)
    return (1.0f - e) * fast_rcp(1.0f + e);
}

// GEMM fragment, gate-quad layout: per k: LDS.64 act (2 rows) + 2x LDS.128 weights (8 cols)
// acc[r][g] = f32x2 over (u0, u0+1) for gate g, batch row m0+r.
template <bool GW, int K>
__device__ __forceinline__ void gemm_q(const float* __restrict__ aT,
                                       const float* __restrict__ Wq,
                                       int m0, int w8, u64 acc[2][4])
{
#pragma unroll 8
    for (int k = 0; k < K; k++) {
        float2 hv = *(const float2*)(aT + k * ST + m0);
        const float* wp = Wq + k * GATES + w8;
        ulonglong2 wv0, wv1;
        if (GW) {
            wv0 = __ldg((const ulonglong2*)wp);       // gates 0,1
            wv1 = __ldg((const ulonglong2*)(wp + 4)); // gates 2,3
        } else {
            wv0 = *(const ulonglong2*)wp;
            wv1 = *(const ulonglong2*)(wp + 4);
        }
        u64 a0 = dup2(hv.x);
        acc[0][0] = fma2(a0, wv0.x, acc[0][0]);
        acc[0][1] = fma2(a0, wv0.y, acc[0][1]);
        acc[0][2] = fma2(a0, wv1.x, acc[0][2]);
        acc[0][3] = fma2(a0, wv1.y, acc[0][3]);
        u64 a1 = dup2(hv.y);
        acc[1][0] = fma2(a1, wv0.x, acc[1][0]);
        acc[1][1] = fma2(a1, wv0.y, acc[1][1]);
        acc[1][2] = fma2(a1, wv1.x, acc[1][2]);
        acc[1][3] = fma2(a1, wv1.y, acc[1][3]);
    }
}

__device__ __forceinline__ void acc_init(const float* __restrict__ sB, int w8, u64 acc[2][4])
{
    ulonglong2 b0 = *(const ulonglong2*)(sB + w8);
    ulonglong2 b1 = *(const ulonglong2*)(sB + w8 + 4);
    acc[0][0] = b0.x; acc[0][1] = b0.y; acc[0][2] = b1.x; acc[0][3] = b1.y;
    acc[1][0] = b0.x; acc[1][1] = b0.y; acc[1][2] = b1.x; acc[1][3] = b1.y;
}

// update 2 rows x 2 cells; cells u0, u0+1; rows m0, m0+1
__device__ __forceinline__ void lstm_update(const u64 acc[2][4], float c[2][2],
                                            float* __restrict__ hT, int m0, int u0)
{
    float h[2][2];
#pragma unroll
    for (int r = 0; r < 2; r++) {
        float2 pi = unpack2(acc[r][0]);
        float2 pf = unpack2(acc[r][1]);
        float2 pg = unpack2(acc[r][2]);
        float2 po = unpack2(acc[r][3]);
        {
            float iv = sigf(pi.x), fv = sigf(pf.x), gv = tanhf_fast(pg.x), ov = sigf(po.x);
            float cc = fv * c[r][0] + iv * gv;
            c[r][0] = cc;
            h[r][0] = ov * tanhf_fast(cc);
        }
        {
            float iv = sigf(pi.y), fv = sigf(pf.y), gv = tanhf_fast(pg.y), ov = sigf(po.y);
            float cc = fv * c[r][1] + iv * gv;
            c[r][1] = cc;
            h[r][1] = ov * tanhf_fast(cc);
        }
    }
    *(float2*)(hT + (u0 + 0) * ST + m0) = make_float2(h[0][0], h[1][0]);
    *(float2*)(hT + (u0 + 1) * ST + m0) = make_float2(h[0][1], h[1][1]);
}

// Shared layout (floats)
#define OFF_W0   0
#define OFF_W1   (OFF_W0 + HID * GATES)
#define OFF_B0   (OFF_W1 + 2 * HID * GATES)
#define OFF_B1   (OFF_B0 + GATES)
#define OFF_H0T  (OFF_B1 + GATES)
#define OFF_H1T  (OFF_H0T + HID * ST)
#define OFF_XT   (OFF_H1T + HID * ST)
#define SMEM_FLOATS (OFF_XT + DIN * ST)   // 55424 floats = 221696 B

__global__ void __launch_bounds__(NTHR, 1)
lstm_fused(const float* __restrict__ x,
           const float* __restrict__ W1h, const float* __restrict__ b1h,
           const float* __restrict__ W2h, const float* __restrict__ b2h,
           float* __restrict__ out)
{
    extern __shared__ float sm[];
    float* sW0 = sm + OFF_W0;              // Whh0 quad
    float* sW1 = sm + OFF_W1;              // [Wih1;Whh1] quad
    float* sB0 = sm + OFF_B0;
    float* sB1 = sm + OFF_B1;
    float* h0T = sm + OFF_H0T;
    float* h1T = sm + OFF_H1T;
    float* xT  = sm + OFF_XT;

    const int tid = threadIdx.x;
    const int b0  = blockIdx.x * BT;

    // stage weights + zero states
    for (int i = tid; i < HID * GATES / 4; i += NTHR)
        ((float4*)sW0)[i] = ((const float4*)g_W0q)[i];
    for (int i = tid; i < 2 * HID * GATES / 4; i += NTHR)
        ((float4*)sW1)[i] = ((const float4*)g_W1q)[i];
    if (tid < GATES) { sB0[tid] = g_b0q[tid]; sB1[tid] = g_b1q[tid]; }
    for (int i = tid; i < 2 * HID * ST; i += NTHR) h0T[i] = 0.0f;  // h0T+h1T contiguous

    // thread tile: rows m0, m0+1; cells u0, u0+1 (gate-quad block w8)
    const int gm = tid & 15;
    const int gn = tid >> 4;
    const int m0 = gm * 2;
    const int u0 = gn * 2;
    const int w8 = gn * 8;

    float c0[2][2] = {{0.f, 0.f}, {0.f, 0.f}};
    float c1[2][2] = {{0.f, 0.f}, {0.f, 0.f}};
    u64 acc0[2][4], acc1[2][4];

    // x staging: thread -> (row xm, float2 chunk xd)
    const int xm = tid >> 4;
    const int xd = tid & 15;
    const float* xrow = x + (size_t)(b0 + xm) * SEQT * DIN + xd * 2;

    // prologue: stage x(0); acc0 = b0 + Wih0*x(0)  (h0(-1)=0)
    float2 xv = *(const float2*)(xrow);
    xT[(2 * xd + 0) * ST + xm] = xv.x;
    xT[(2 * xd + 1) * ST + xm] = xv.y;
    __syncthreads();

    acc_init(sB0, w8, acc0);
    gemm_q<true, DIN>(xT, g_Wx0q, m0, w8, acc0);
    xv = *(const float2*)(xrow + DIN);        // x(1)
    __syncthreads();                          // xT readers done before restage

    for (int t = 0; t < SEQT; t++) {
        // ---- P1: update0(t) (MUFU) || Whh1*h1(t-1) (FFMA) + stage x(t+1)
        lstm_update(acc0, c0, h0T, m0, u0);            // writes h0(t)
        acc_init(sB1, w8, acc1);
        gemm_q<false, HID>(h1T, sW1 + HID * GATES, m0, w8, acc1);  // Whh1*h1(t-1)
        xT[(2 * xd + 0) * ST + xm] = xv.x;             // stage x(t+1)
        xT[(2 * xd + 1) * ST + xm] = xv.y;
        {
            int tn = (t + 2 < SEQT) ? t + 2 : SEQT - 1;
            xv = *(const float2*)(xrow + (size_t)tn * DIN);  // prefetch x(t+2)
        }
        __syncthreads();                               // B1: h0(t), x(t+1) visible

        // ---- P2: Wih1*h0(t) + Whh0[0:32]*h0(t) + Wih0*x(t+1)  (pure FFMA)
        gemm_q<false, HID>(h0T, sW1, m0, w8, acc1);    // Wih1*h0(t)
        acc_init(sB0, w8, acc0);
        gemm_q<false, 32>(h0T, sW0, m0, w8, acc0);     // Whh0 k:0..31
        gemm_q<true, DIN>(xT, g_Wx0q, m0, w8, acc0);   // Wih0*x(t+1)

        // ---- P3 (no barrier): Whh0[32:64] (FFMA) || update1(t) (MUFU)
        gemm_q<false, 32>(h0T + 32 * ST, sW0 + 32 * GATES, m0, w8, acc0);
        lstm_update(acc1, c1, h1T, m0, u0);            // writes h1(t)
        __syncthreads();                               // B2: h1(t) visible
    }

    // ---- head: out[m] = b2 + sum_n W2[n]*relu(b1[n] + sum_k h1(k,m) W1[n,k]) ----
    {
        int m = tid >> 4;      // 0..31
        int q = tid & 15;      // 0..15
        float pm = 0.0f;
#pragma unroll
        for (int jj = 0; jj < 4; jj++) {
            int n = q * 4 + jj;
            float s = b1h[n];
#pragma unroll 8
            for (int k = 0; k < HID; k++)
                s += h1T[k * ST + m] * W1h[n * HID + k];
            pm += fmaxf(s, 0.0f) * W2h[n];
        }
#pragma unroll
        for (int off = 8; off > 0; off >>= 1)
            pm += __shfl_down_sync(0xffffffffu, pm, off, 16);
        if (q == 0) out[b0 + m] = pm + b2h[0];
    }
}

extern "C" void kernel_launch(void* const* d_in, const int* in_sizes, int n_in,
                              void* d_out, int out_size)
{
    const float* x    = (const float*)d_in[0];
    const float* Wih0 = (const float*)d_in[1];
    const float* Whh0 = (const float*)d_in[2];
    const float* bih0 = (const float*)d_in[3];
    const float* bhh0 = (const float*)d_in[4];
    const float* Wih1 = (const float*)d_in[5];
    const float* Whh1 = (const float*)d_in[6];
    const float* bih1 = (const float*)d_in[7];
    const float* bhh1 = (const float*)d_in[8];
    const float* W1   = (const float*)d_in[9];
    const float* b1   = (const float*)d_in[10];
    const float* W2   = (const float*)d_in[11];
    const float* b2   = (const float*)d_in[12];

    prep_kernel<<<64, 256>>>(Wih0, Whh0, bih0, bhh0, Wih1, Whh1, bih1, bhh1);

    size_t smem_bytes = (size_t)SMEM_FLOATS * sizeof(float);  // 221696 B
    cudaFuncSetAttribute(lstm_fused,
                         cudaFuncAttributeMaxDynamicSharedMemorySize, (int)smem_bytes);
    lstm_fused<<<NCTA, NTHR, smem_bytes>>>(x, W1, b1, W2, b2, (float*)d_out);
}

// round 10
// speedup vs baseline: 1.1455x; 1.1455x over previous
#include <cuda_runtime.h>

#define BATCH 4096
#define SEQT  256
#define DIN   32
#define HID   64
#define GATES 256
#define BT    32
#define NTHR  512
#define NCTA  128
#define ST    36

typedef unsigned long long u64;

// ---- gate-quad weight layout W[k][u2][g][upar]: n = g*64 + u2*2 + up ----
__device__ __align__(16) float g_W0q[HID * GATES];     // Whh0 quad
__device__ __align__(16) float g_Wx0q[DIN * GATES];    // Wih0 quad (per-step LDG)
__device__ __align__(16) float g_W1q[2 * HID * GATES]; // [Wih1; Whh1] quad
__device__ __align__(16) float g_b0q[GATES];
__device__ __align__(16) float g_b1q[GATES];

__global__ void prep_kernel(const float* __restrict__ Wih0, const float* __restrict__ Whh0,
                            const float* __restrict__ bih0, const float* __restrict__ bhh0,
                            const float* __restrict__ Wih1, const float* __restrict__ Whh1,
                            const float* __restrict__ bih1, const float* __restrict__ bhh1)
{
    int idx = blockIdx.x * blockDim.x + threadIdx.x;
    int stride = gridDim.x * blockDim.x;
    for (int j = idx; j < HID * GATES; j += stride) {
        int k = j / GATES, r = j % GATES;
        int n = ((r >> 1) & 3) * HID + (r >> 3) * 2 + (r & 1);
        g_W0q[j] = Whh0[n * HID + k];
    }
    for (int j = idx; j < DIN * GATES; j += stride) {
        int k = j / GATES, r = j % GATES;
        int n = ((r >> 1) & 3) * HID + (r >> 3) * 2 + (r & 1);
        g_Wx0q[j] = Wih0[n * DIN + k];
    }
    for (int j = idx; j < 2 * HID * GATES; j += stride) {
        int k = j / GATES, r = j % GATES;
        int n = ((r >> 1) & 3) * HID + (r >> 3) * 2 + (r & 1);
        g_W1q[j] = (k < HID) ? Wih1[n * HID + k] : Whh1[n * HID + (k - HID)];
    }
    for (int r = idx; r < GATES; r += stride) {
        int n = ((r >> 1) & 3) * HID + (r >> 3) * 2 + (r & 1);
        g_b0q[r] = bih0[n] + bhh0[n];
        g_b1q[r] = bih1[n] + bhh1[n];
    }
}

// ---- packed f32x2 helpers ----
__device__ __forceinline__ u64 fma2(u64 a, u64 b, u64 c) {
    u64 d;
    asm("fma.rn.f32x2 %0, %1, %2, %3;" : "=l"(d) : "l"(a), "l"(b), "l"(c));
    return d;
}
__device__ __forceinline__ u64 add2(u64 a, u64 b) {
    u64 d;
    asm("add.rn.f32x2 %0, %1, %2;" : "=l"(d) : "l"(a), "l"(b));
    return d;
}
__device__ __forceinline__ u64 dup2(float x) {
    u64 d;
    asm("mov.b64 %0, {%1, %1};" : "=l"(d) : "f"(x));
    return d;
}
__device__ __forceinline__ float2 unpack2(u64 v) {
    float2 f;
    asm("mov.b64 {%0, %1}, %2;" : "=f"(f.x), "=f"(f.y) : "l"(v));
    return f;
}

// ---- fast activations ----
__device__ __forceinline__ float fast_ex2(float x) {
    float y; asm("ex2.approx.f32 %0, %1;" : "=f"(y) : "f"(x)); return y;
}
__device__ __forceinline__ float fast_rcp(float x) {
    float y; asm("rcp.approx.f32 %0, %1;" : "=f"(y) : "f"(x)); return y;
}
__device__ __forceinline__ float sigf(float x) {
    return fast_rcp(1.0f + fast_ex2(-1.4426950408889634f * x));
}
__device__ __forceinline__ float tanhf_fast(float x) {
    x = fminf(fmaxf(x, -15.0f), 15.0f);
    float e = fast_ex2(-2.8853900817779268f * x);
    return (1.0f - e) * fast_rcp(1.0f + e);
}

// GEMM fragment: 4 rows x 8 cols (quad layout), per k: 1 LDS.128 act + 2 LDS.128 weights
template <bool GW, int K>
__device__ __forceinline__ void gemm_q4(const float* __restrict__ aT,
                                        const float* __restrict__ Wq,
                                        int m0, int w8, u64 acc[4][4])
{
#pragma unroll 4
    for (int k = 0; k < K; k++) {
        float4 hv = *(const float4*)(aT + k * ST + m0);
        const float* wp = Wq + k * GATES + w8;
        ulonglong2 wv0, wv1;
        if (GW) {
            wv0 = __ldg((const ulonglong2*)wp);
            wv1 = __ldg((const ulonglong2*)(wp + 4));
        } else {
            wv0 = *(const ulonglong2*)wp;
            wv1 = *(const ulonglong2*)(wp + 4);
        }
        u64 a;
        a = dup2(hv.x);
        acc[0][0] = fma2(a, wv0.x, acc[0][0]);
        acc[0][1] = fma2(a, wv0.y, acc[0][1]);
        acc[0][2] = fma2(a, wv1.x, acc[0][2]);
        acc[0][3] = fma2(a, wv1.y, acc[0][3]);
        a = dup2(hv.y);
        acc[1][0] = fma2(a, wv0.x, acc[1][0]);
        acc[1][1] = fma2(a, wv0.y, acc[1][1]);
        acc[1][2] = fma2(a, wv1.x, acc[1][2]);
        acc[1][3] = fma2(a, wv1.y, acc[1][3]);
        a = dup2(hv.z);
        acc[2][0] = fma2(a, wv0.x, acc[2][0]);
        acc[2][1] = fma2(a, wv0.y, acc[2][1]);
        acc[2][2] = fma2(a, wv1.x, acc[2][2]);
        acc[2][3] = fma2(a, wv1.y, acc[2][3]);
        a = dup2(hv.w);
        acc[3][0] = fma2(a, wv0.x, acc[3][0]);
        acc[3][1] = fma2(a, wv0.y, acc[3][1]);
        acc[3][2] = fma2(a, wv1.x, acc[3][2]);
        acc[3][3] = fma2(a, wv1.y, acc[3][3]);
    }
}

// bias init: ks==0 lane carries bias, ks==1 lane zero (bias counted once after reduce)
__device__ __forceinline__ void acc_init4(const float* __restrict__ sB, int w8, int ks,
                                          u64 acc[4][4])
{
    u64 b0 = 0, b1 = 0, b2 = 0, b3 = 0;
    if (!ks) {
        ulonglong2 p0 = *(const ulonglong2*)(sB + w8);
        ulonglong2 p1 = *(const ulonglong2*)(sB + w8 + 4);
        b0 = p0.x; b1 = p0.y; b2 = p1.x; b3 = p1.y;
    }
#pragma unroll
    for (int r = 0; r < 4; r++) {
        acc[r][0] = b0; acc[r][1] = b1; acc[r][2] = b2; acc[r][3] = b3;
    }
}

// combine k-halves across lane pairs (l <-> l^16); thread keeps 2 rows
__device__ __forceinline__ void reduce4(const u64 acc[4][4], int ks, u64 s[2][4])
{
#pragma unroll
    for (int r = 0; r < 2; r++) {
#pragma unroll
        for (int g = 0; g < 4; g++) {
            u64 send = ks ? acc[r][g] : acc[r + 2][g];
            u64 got  = __shfl_xor_sync(0xffffffffu, send, 16);
            u64 mine = ks ? acc[r + 2][g] : acc[r][g];
            s[r][g] = add2(mine, got);
        }
    }
}

// update 2 rows x 2 cells; rows mb, mb+1; cells u0, u0+1
__device__ __forceinline__ void lstm_update2(const u64 s[2][4], float c[2][2],
                                             float* __restrict__ hT, int mb, int u0)
{
    float h[2][2];
#pragma unroll
    for (int r = 0; r < 2; r++) {
        float2 pi = unpack2(s[r][0]);
        float2 pf = unpack2(s[r][1]);
        float2 pg = unpack2(s[r][2]);
        float2 po = unpack2(s[r][3]);
        {
            float iv = sigf(pi.x), fv = sigf(pf.x), gv = tanhf_fast(pg.x), ov = sigf(po.x);
            float cc = fv * c[r][0] + iv * gv;
            c[r][0] = cc;
            h[r][0] = ov * tanhf_fast(cc);
        }
        {
            float iv = sigf(pi.y), fv = sigf(pf.y), gv = tanhf_fast(pg.y), ov = sigf(po.y);
            float cc = fv * c[r][1] + iv * gv;
            c[r][1] = cc;
            h[r][1] = ov * tanhf_fast(cc);
        }
    }
    *(float2*)(hT + (u0 + 0) * ST + mb) = make_float2(h[0][0], h[1][0]);
    *(float2*)(hT + (u0 + 1) * ST + mb) = make_float2(h[0][1], h[1][1]);
}

// Shared layout (floats)
#define OFF_W0   0
#define OFF_W1   (OFF_W0 + HID * GATES)
#define OFF_B0   (OFF_W1 + 2 * HID * GATES)
#define OFF_B1   (OFF_B0 + GATES)
#define OFF_H0T  (OFF_B1 + GATES)
#define OFF_H1T  (OFF_H0T + HID * ST)
#define OFF_XT   (OFF_H1T + HID * ST)
#define SMEM_FLOATS (OFF_XT + DIN * ST)   // 221696 B

__global__ void __launch_bounds__(NTHR, 1)
lstm_fused(const float* __restrict__ x,
           const float* __restrict__ W1h, const float* __restrict__ b1h,
           const float* __restrict__ W2h, const float* __restrict__ b2h,
           float* __restrict__ out)
{
    extern __shared__ float sm[];
    float* sW0 = sm + OFF_W0;
    float* sW1 = sm + OFF_W1;
    float* sB0 = sm + OFF_B0;
    float* sB1 = sm + OFF_B1;
    float* h0T = sm + OFF_H0T;
    float* h1T = sm + OFF_H1T;
    float* xT  = sm + OFF_XT;

    const int tid = threadIdx.x;
    const int b0  = blockIdx.x * BT;

    // stage weights + zero states
    for (int i = tid; i < HID * GATES / 4; i += NTHR)
        ((float4*)sW0)[i] = ((const float4*)g_W0q)[i];
    for (int i = tid; i < 2 * HID * GATES / 4; i += NTHR)
        ((float4*)sW1)[i] = ((const float4*)g_W1q)[i];
    if (tid < GATES) { sB0[tid] = g_b0q[tid]; sB1[tid] = g_b1q[tid]; }
    for (int i = tid; i < 2 * HID * ST; i += NTHR) h0T[i] = 0.0f;

    // k-split pair mapping: tile idx = warp*16 + (lane&15); ks = lane>>4
    const int lane = tid & 31;
    const int ks   = lane >> 4;
    const int idx  = (tid >> 5) * 16 + (lane & 15);   // 0..255
    const int gm   = idx & 7;
    const int gn   = idx >> 3;                        // 0..31
    const int m0   = gm * 4;
    const int u0   = gn * 2;
    const int w8   = gn * 8;
    const int mb   = m0 + 2 * ks;                     // rows this thread finalizes

    // per-k-half base pointers
    const float* h0T_k  = h0T + ks * 32 * ST;
    const float* h1T_k  = h1T + ks * 32 * ST;
    const float* xT_k   = xT  + ks * 16 * ST;
    const float* sW0_k  = sW0 + ks * 32 * GATES;              // Whh0 half
    const float* sW1a_k = sW1 + ks * 32 * GATES;              // Wih1 half
    const float* sW1b_k = sW1 + HID * GATES + ks * 32 * GATES;// Whh1 half
    const float* gWx_k  = g_Wx0q + ks * 16 * GATES;           // Wih0 half

    float c0[2][2] = {{0.f, 0.f}, {0.f, 0.f}};
    float c1[2][2] = {{0.f, 0.f}, {0.f, 0.f}};
    u64 acc[4][4];
    u64 s[2][4];

    // x staging: thread -> (row xm, float2 chunk xd)
    const int xm = tid >> 4;
    const int xd = tid & 15;
    const float* xrow = x + (size_t)(b0 + xm) * SEQT * DIN + xd * 2;

    // prologue: stage x(0); acc = b0 + Wih0*x(0) + Whh0*0
    float2 xv = *(const float2*)(xrow);
    xT[(2 * xd + 0) * ST + xm] = xv.x;
    xT[(2 * xd + 1) * ST + xm] = xv.y;
    __syncthreads();

    acc_init4(sB0, w8, ks, acc);
    gemm_q4<true, 16>(xT_k, gWx_k, m0, w8, acc);
    gemm_q4<false, 32>(h0T_k, sW0_k, m0, w8, acc);  // h0=0, keeps flow uniform
    xv = *(const float2*)(xrow + DIN);               // x(1)

    for (int t = 0; t < SEQT; t++) {
        __syncthreads();                             // B1: gemm0(t) done everywhere

        // ---- phase 2: reduce0 -> acc free; Whh1*h1(t-1) (FFMA) || update0 (MUFU); stage x(t+1)
        reduce4(acc, ks, s);
        acc_init4(sB1, w8, ks, acc);
        gemm_q4<false, 32>(h1T_k, sW1b_k, m0, w8, acc);   // Whh1*h1(t-1)
        lstm_update2(s, c0, h0T, mb, u0);                 // writes h0(t)
        xT[(2 * xd + 0) * ST + xm] = xv.x;                // stage x(t+1)
        xT[(2 * xd + 1) * ST + xm] = xv.y;
        {
            int tn = (t + 2 < SEQT) ? t + 2 : SEQT - 1;
            xv = *(const float2*)(xrow + (size_t)tn * DIN);
        }
        __syncthreads();                             // B2: h0(t), x(t+1) visible

        // ---- phase 4: Wih1*h0(t)
        gemm_q4<false, 32>(h0T_k, sW1a_k, m0, w8, acc);
        __syncthreads();                             // B3: gemm1 reads done

        // ---- phase 6: reduce1 + update1 (MUFU) || gemm0(t+1) (FFMA)
        reduce4(acc, ks, s);
        acc_init4(sB0, w8, ks, acc);
        gemm_q4<true, 16>(xT_k, gWx_k, m0, w8, acc);      // Wih0*x(t+1)
        gemm_q4<false, 32>(h0T_k, sW0_k, m0, w8, acc);    // Whh0*h0(t)
        lstm_update2(s, c1, h1T, mb, u0);                 // writes h1(t)
    }
    __syncthreads();

    // ---- head: out[m] = b2 + sum_n W2[n]*relu(b1[n] + sum_k h1(k,m) W1[n,k]) ----
    {
        int m = tid >> 4;      // 0..31
        int q = tid & 15;      // 0..15
        float pm = 0.0f;
#pragma unroll
        for (int jj = 0; jj < 4; jj++) {
            int n = q * 4 + jj;
            float sv = b1h[n];
#pragma unroll 8
            for (int k = 0; k < HID; k++)
                sv += h1T[k * ST + m] * W1h[n * HID + k];
            pm += fmaxf(sv, 0.0f) * W2h[n];
        }
#pragma unroll
        for (int off = 8; off > 0; off >>= 1)
            pm += __shfl_down_sync(0xffffffffu, pm, off, 16);
        if (q == 0) out[b0 + m] = pm + b2h[0];
    }
}

extern "C" void kernel_launch(void* const* d_in, const int* in_sizes, int n_in,
                              void* d_out, int out_size)
{
    const float* x    = (const float*)d_in[0];
    const float* Wih0 = (const float*)d_in[1];
    const float* Whh0 = (const float*)d_in[2];
    const float* bih0 = (const float*)d_in[3];
    const float* bhh0 = (const float*)d_in[4];
    const float* Wih1 = (const float*)d_in[5];
    const float* Whh1 = (const float*)d_in[6];
    const float* bih1 = (const float*)d_in[7];
    const float* bhh1 = (const float*)d_in[8];
    const float* W1   = (const float*)d_in[9];
    const float* b1   = (const float*)d_in[10];
    const float* W2   = (const float*)d_in[11];
    const float* b2   = (const float*)d_in[12];

    prep_kernel<<<64, 256>>>(Wih0, Whh0, bih0, bhh0, Wih1, Whh1, bih1, bhh1);

    size_t smem_bytes = (size_t)SMEM_FLOATS * sizeof(float);
    cudaFuncSetAttribute(lstm_fused,
                         cudaFuncAttributeMaxDynamicSharedMemorySize, (int)smem_bytes);
    lstm_fused<<<NCTA, NTHR, smem_bytes>>>(x, W1, b1, W2, b2, (float*)d_out);
}